// round 6
// baseline (speedup 1.0000x reference)
#include <cuda_runtime.h>
#include <math.h>

// result = sum_{b,t} w^2 * log(sigmoid(logit)+EPS) * log_probs * (t+1) / sum(w)
// (reversed cumsum then total sum == (t+1)-weighted sum)
//
// R4: MLP-batched variant. Each thread owns ITERS=4 float4 triples,
// stride-partitioned; all 12 LDG.128 issued before any compute so the
// L1tex queue is fed (MLP_p1 ~= 12 vs ~3 in the grid-stride version).
// Single fused kernel, self-resetting atomic counter (graph-replay safe).

#define T_DIM    16384          // inner dim (power of 2)
#define EPS_F    1e-7f
#define NTHREADS 256
#define ITERS    4
#define MAXBLOCKS 4096

__device__ double        g_part_t[MAXBLOCKS];
__device__ double        g_part_w[MAXBLOCKS];
__device__ unsigned int  g_count;   // zero-init at load; wraps to 0 every pass

__device__ __forceinline__ float term_elem(float lp, float lg, float w, float tscale) {
    float e = __expf(-lg);                       // MUFU.EX2 path
    float s = __fdividef(1.0f, 1.0f + e);        // MUFU.RCP
    float r = __logf(s + EPS_F);                 // MUFU.LG2
    return w * w * r * lp * tscale;
}

__device__ __forceinline__ float quad_term(float4 a, float4 b, float4 c, int idx4) {
    int   t0 = (idx4 << 2) & (T_DIM - 1);
    float tw = (float)(t0 + 1);
    float s  = term_elem(a.x, b.x, c.x, tw);
    s += term_elem(a.y, b.y, c.y, tw + 1.0f);
    s += term_elem(a.z, b.z, c.z, tw + 2.0f);
    s += term_elem(a.w, b.w, c.w, tw + 3.0f);
    return s;
}

__device__ __forceinline__ double dbl_shfl_down(double v, int off) {
    return __shfl_down_sync(0xffffffffu, v, off);
}

__global__ void __launch_bounds__(NTHREADS)
reinforce_kernel(const float4* __restrict__ lp,
                 const float4* __restrict__ lg,
                 const float4* __restrict__ w,
                 int n4,
                 float* __restrict__ out)
{
    const int tid  = blockIdx.x * blockDim.x + threadIdx.x;
    const int step = gridDim.x * blockDim.x;

    float acc_t = 0.0f;
    float acc_w = 0.0f;

    if (ITERS * step == n4) {
        // exact partition: batch all loads first (12 independent LDG.128)
        const int i0 = tid;
        const int i1 = tid + step;
        const int i2 = tid + 2 * step;
        const int i3 = tid + 3 * step;

        float4 a0 = lp[i0], a1 = lp[i1], a2 = lp[i2], a3 = lp[i3];
        float4 b0 = lg[i0], b1 = lg[i1], b2 = lg[i2], b3 = lg[i3];
        float4 c0 = w[i0],  c1 = w[i1],  c2 = w[i2],  c3 = w[i3];

        acc_t  = quad_term(a0, b0, c0, i0);
        acc_t += quad_term(a1, b1, c1, i1);
        acc_t += quad_term(a2, b2, c2, i2);
        acc_t += quad_term(a3, b3, c3, i3);
        acc_w  = (c0.x + c0.y) + (c0.z + c0.w)
               + (c1.x + c1.y) + (c1.z + c1.w)
               + (c2.x + c2.y) + (c2.z + c2.w)
               + (c3.x + c3.y) + (c3.z + c3.w);
    } else {
        // generic fallback (not taken for this problem's shape)
        for (int i = tid; i < n4; i += step) {
            float4 a = lp[i], b = lg[i], c = w[i];
            acc_t += quad_term(a, b, c, i);
            acc_w += (c.x + c.y) + (c.z + c.w);
        }
    }

    // ---- block reduce (fp32) ----
    #pragma unroll
    for (int off = 16; off > 0; off >>= 1) {
        acc_t += __shfl_down_sync(0xffffffffu, acc_t, off);
        acc_w += __shfl_down_sync(0xffffffffu, acc_w, off);
    }

    __shared__ float st[NTHREADS / 32];
    __shared__ float sw[NTHREADS / 32];
    const int lane = threadIdx.x & 31;
    const int wid  = threadIdx.x >> 5;
    if (lane == 0) { st[wid] = acc_t; sw[wid] = acc_w; }
    __syncthreads();

    __shared__ bool s_last;
    if (threadIdx.x == 0) {
        float bt = 0.0f, bw = 0.0f;
        #pragma unroll
        for (int k = 0; k < NTHREADS / 32; k++) { bt += st[k]; bw += sw[k]; }
        g_part_t[blockIdx.x] = (double)bt;
        g_part_w[blockIdx.x] = (double)bw;
        __threadfence();
        unsigned int prev = atomicInc(&g_count, gridDim.x - 1);
        s_last = (prev == gridDim.x - 1);
    }
    __syncthreads();

    // ---- last block: reduce partials in double, write scalar ----
    if (s_last) {
        double dt = 0.0, dw = 0.0;
        for (int k = threadIdx.x; k < gridDim.x; k += NTHREADS) {
            dt += g_part_t[k];
            dw += g_part_w[k];
        }
        #pragma unroll
        for (int off = 16; off > 0; off >>= 1) {
            dt += dbl_shfl_down(dt, off);
            dw += dbl_shfl_down(dw, off);
        }
        __shared__ double dst[NTHREADS / 32];
        __shared__ double dsw[NTHREADS / 32];
        if (lane == 0) { dst[wid] = dt; dsw[wid] = dw; }
        __syncthreads();
        if (threadIdx.x == 0) {
            double ft = 0.0, fw = 0.0;
            #pragma unroll
            for (int k = 0; k < NTHREADS / 32; k++) { ft += dst[k]; fw += dsw[k]; }
            out[0] = (float)(ft / fw);
        }
    }
}

extern "C" void kernel_launch(void* const* d_in, const int* in_sizes, int n_in,
                              void* d_out, int out_size) {
    const float4* lp = (const float4*)d_in[0];
    const float4* lg = (const float4*)d_in[1];
    const float4* w  = (const float4*)d_in[2];
    float* out = (float*)d_out;

    const int n  = in_sizes[0];   // B*T
    const int n4 = n >> 2;

    // exact partition: n4 = blocks * NTHREADS * ITERS when divisible
    int blocks = n4 / (NTHREADS * ITERS);
    if (blocks < 1) blocks = 1;
    if (blocks > MAXBLOCKS) blocks = MAXBLOCKS;          // falls back to loop path
    if (blocks * NTHREADS * ITERS != n4) {
        blocks = (n4 + NTHREADS - 1) / NTHREADS;         // generic fallback
        if (blocks > MAXBLOCKS) blocks = MAXBLOCKS;
    }

    reinforce_kernel<<<blocks, NTHREADS>>>(lp, lg, w, n4, out);
}